// round 1
// baseline (speedup 1.0000x reference)
#include <cuda_runtime.h>
#include <math.h>

#define T_TOK 8192
#define D_DIM 1024
#define F_DIM 2048
#define E_EXP 8
#define KSEL  2
#define CAP   8192   // per-expert worst-case capacity

#define BM 64
#define BN 64
#define BK 16

// Scratch (allocation-free rule: __device__ globals)
__device__ float  g_H[(size_t)E_EXP * CAP * F_DIM];   // SwiGLU activations per assignment slot
__device__ int    g_cnt[E_EXP];
__device__ int    g_tok[E_EXP * CAP];
__device__ float  g_wt [E_EXP * CAP];
__device__ double g_psum[E_EXP];
__device__ double g_zsum;

__global__ void init_kernel() {
    int i = threadIdx.x;
    if (i < E_EXP) { g_cnt[i] = 0; g_psum[i] = 0.0; }
    if (i == 0) g_zsum = 0.0;
}

// One warp per token (grid-stride). Computes logits = x@Wr, softmax, top-2,
// renormalized combine weights, appends (token, weight) to its experts'
// segments, and accumulates aux-loss statistics (block-reduced, then global
// double atomics to keep contention trivial).
__global__ void router_kernel(const float* __restrict__ x,
                              const float* __restrict__ Wr) {
    __shared__ double s_ps[E_EXP];
    __shared__ double s_zs;
    int tid = threadIdx.x;
    if (tid < E_EXP) s_ps[tid] = 0.0;
    if (tid == 0) s_zs = 0.0;
    __syncthreads();

    int lane = tid & 31;
    int warp = tid >> 5;
    int nwarps_total = (gridDim.x * blockDim.x) >> 5;
    int gwarp = blockIdx.x * (blockDim.x >> 5) + warp;

    double lps[E_EXP];
#pragma unroll
    for (int e = 0; e < E_EXP; e++) lps[e] = 0.0;
    double lzs = 0.0;

    for (int t = gwarp; t < T_TOK; t += nwarps_total) {
        const float* xr = x + (size_t)t * D_DIM;
        float acc[E_EXP];
#pragma unroll
        for (int e = 0; e < E_EXP; e++) acc[e] = 0.f;
        for (int i = lane; i < D_DIM; i += 32) {
            float xv = xr[i];
#pragma unroll
            for (int e = 0; e < E_EXP; e++)
                acc[e] = fmaf(xv, Wr[i * E_EXP + e], acc[e]);
        }
#pragma unroll
        for (int e = 0; e < E_EXP; e++) {
#pragma unroll
            for (int o = 16; o > 0; o >>= 1)
                acc[e] += __shfl_xor_sync(0xffffffffu, acc[e], o);
        }
        if (lane == 0) {
            float m = acc[0];
#pragma unroll
            for (int e = 1; e < E_EXP; e++) m = fmaxf(m, acc[e]);
            float s = 0.f, p[E_EXP];
#pragma unroll
            for (int e = 0; e < E_EXP; e++) { p[e] = expf(acc[e] - m); s += p[e]; }
            float inv = 1.f / s;
#pragma unroll
            for (int e = 0; e < E_EXP; e++) { p[e] *= inv; lps[e] += (double)p[e]; }
            float lse = m + logf(s);
            lzs += (double)lse * (double)lse;

            // top-2 (by logits; softmax is monotone). First index wins ties.
            int i0 = 0; float v0 = acc[0];
#pragma unroll
            for (int e = 1; e < E_EXP; e++) if (acc[e] > v0) { v0 = acc[e]; i0 = e; }
            int i1 = -1; float v1 = -INFINITY;
#pragma unroll
            for (int e = 0; e < E_EXP; e++)
                if (e != i0 && acc[e] > v1) { v1 = acc[e]; i1 = e; }

            float pv0 = p[i0], pv1 = p[i1];
            float rinv = 1.f / (pv0 + pv1);
            float w0 = pv0 * rinv, w1 = pv1 * rinv;

            int pos0 = atomicAdd(&g_cnt[i0], 1);
            g_tok[i0 * CAP + pos0] = t; g_wt[i0 * CAP + pos0] = w0;
            int pos1 = atomicAdd(&g_cnt[i1], 1);
            g_tok[i1 * CAP + pos1] = t; g_wt[i1 * CAP + pos1] = w1;
        }
    }
    if (lane == 0) {
#pragma unroll
        for (int e = 0; e < E_EXP; e++) atomicAdd(&s_ps[e], lps[e]);
        atomicAdd(&s_zs, lzs);
    }
    __syncthreads();
    if (tid < E_EXP) atomicAdd(&g_psum[tid], s_ps[tid]);
    if (tid == 0) atomicAdd(&g_zsum, s_zs);
}

// GEMM1: H[slot] = silu(X_e @ Wg_e) * (X_e @ Wu_e)
// 64x64 tile, BK=16, 256 threads, 4x4 register tile per matrix (G and U share A).
__global__ void gemm1_kernel(const float* __restrict__ x,
                             const float* __restrict__ Wg,
                             const float* __restrict__ Wu) {
    int e = blockIdx.z;
    int n = g_cnt[e];
    int row0 = blockIdx.y * BM;
    if (row0 >= n) return;
    int col0 = blockIdx.x * BN;

    __shared__ float Xs[BM][BK + 1];
    __shared__ float Gs[BK][BN];
    __shared__ float Us[BK][BN];
    __shared__ int   toks[BM];

    int tid = threadIdx.x;
    if (tid < BM) {
        int r = row0 + tid;
        toks[tid] = (r < n) ? g_tok[e * CAP + r] : -1;
    }
    __syncthreads();

    int tx = tid & 15, ty = tid >> 4;
    float accG[4][4] = {}, accU[4][4] = {};
    const float* Wge = Wg + (size_t)e * D_DIM * F_DIM;
    const float* Wue = Wu + (size_t)e * D_DIM * F_DIM;

    int xc = (tid & 3) * 4;   // float4 column within BK
    int xr = tid >> 2;        // 0..63
    int wc = (tid & 15) * 4;  // float4 column within BN
    int wr = tid >> 4;        // 0..15

    int mytok = toks[xr];

    for (int k0 = 0; k0 < D_DIM; k0 += BK) {
        float4 xv = make_float4(0.f, 0.f, 0.f, 0.f);
        if (mytok >= 0)
            xv = *(const float4*)(x + (size_t)mytok * D_DIM + k0 + xc);
        Xs[xr][xc + 0] = xv.x; Xs[xr][xc + 1] = xv.y;
        Xs[xr][xc + 2] = xv.z; Xs[xr][xc + 3] = xv.w;
        *(float4*)&Gs[wr][wc] = *(const float4*)(Wge + (size_t)(k0 + wr) * F_DIM + col0 + wc);
        *(float4*)&Us[wr][wc] = *(const float4*)(Wue + (size_t)(k0 + wr) * F_DIM + col0 + wc);
        __syncthreads();
#pragma unroll
        for (int kk = 0; kk < BK; kk++) {
            float a[4];
#pragma unroll
            for (int i = 0; i < 4; i++) a[i] = Xs[ty * 4 + i][kk];
            float4 bg = *(float4*)&Gs[kk][tx * 4];
            float4 bu = *(float4*)&Us[kk][tx * 4];
            float bgv[4] = {bg.x, bg.y, bg.z, bg.w};
            float buv[4] = {bu.x, bu.y, bu.z, bu.w};
#pragma unroll
            for (int i = 0; i < 4; i++)
#pragma unroll
                for (int j = 0; j < 4; j++) {
                    accG[i][j] = fmaf(a[i], bgv[j], accG[i][j]);
                    accU[i][j] = fmaf(a[i], buv[j], accU[i][j]);
                }
        }
        __syncthreads();
    }

#pragma unroll
    for (int i = 0; i < 4; i++) {
        int row = row0 + ty * 4 + i;
        if (row < n) {
            float4 hv;
            float* hp = &hv.x;
#pragma unroll
            for (int j = 0; j < 4; j++) {
                float g = accG[i][j];
                float sg = g / (1.f + expf(-g));
                hp[j] = sg * accU[i][j];
            }
            *(float4*)&g_H[((size_t)e * CAP + row) * F_DIM + col0 + tx * 4] = hv;
        }
    }
}

// GEMM2: out[tok] += w_slot * (H[slot] @ Wd_e)
__global__ void gemm2_kernel(const float* __restrict__ Wd,
                             float* __restrict__ out) {
    int e = blockIdx.z;
    int n = g_cnt[e];
    int row0 = blockIdx.y * BM;
    if (row0 >= n) return;
    int col0 = blockIdx.x * BN;

    __shared__ float Hs[BM][BK + 1];
    __shared__ float Ds[BK][BN];
    __shared__ int   toks[BM];
    __shared__ float wts[BM];

    int tid = threadIdx.x;
    if (tid < BM) {
        int r = row0 + tid;
        toks[tid] = (r < n) ? g_tok[e * CAP + r] : -1;
        wts[tid]  = (r < n) ? g_wt[e * CAP + r] : 0.f;
    }
    __syncthreads();

    int tx = tid & 15, ty = tid >> 4;
    float acc[4][4] = {};
    const float* Wde = Wd + (size_t)e * F_DIM * D_DIM;
    const float* Hbase = &g_H[((size_t)e * CAP + row0) * F_DIM];

    int xc = (tid & 3) * 4;
    int xr = tid >> 2;
    int wc = (tid & 15) * 4;
    int wr = tid >> 4;
    bool rowok = (row0 + xr) < n;

    for (int k0 = 0; k0 < F_DIM; k0 += BK) {
        float4 hv = make_float4(0.f, 0.f, 0.f, 0.f);
        if (rowok)
            hv = *(const float4*)(Hbase + (size_t)xr * F_DIM + k0 + xc);
        Hs[xr][xc + 0] = hv.x; Hs[xr][xc + 1] = hv.y;
        Hs[xr][xc + 2] = hv.z; Hs[xr][xc + 3] = hv.w;
        *(float4*)&Ds[wr][wc] = *(const float4*)(Wde + (size_t)(k0 + wr) * D_DIM + col0 + wc);
        __syncthreads();
#pragma unroll
        for (int kk = 0; kk < BK; kk++) {
            float a[4];
#pragma unroll
            for (int i = 0; i < 4; i++) a[i] = Hs[ty * 4 + i][kk];
            float4 b = *(float4*)&Ds[kk][tx * 4];
            float bv[4] = {b.x, b.y, b.z, b.w};
#pragma unroll
            for (int i = 0; i < 4; i++)
#pragma unroll
                for (int j = 0; j < 4; j++)
                    acc[i][j] = fmaf(a[i], bv[j], acc[i][j]);
        }
        __syncthreads();
    }

#pragma unroll
    for (int i = 0; i < 4; i++) {
        int r = ty * 4 + i;
        if (row0 + r < n) {
            int tok = toks[r];
            float w = wts[r];
            float* orow = out + (size_t)tok * D_DIM + col0 + tx * 4;
#pragma unroll
            for (int j = 0; j < 4; j++)
                atomicAdd(&orow[j], w * acc[i][j]);
        }
    }
}

__global__ void finalize_kernel(float* __restrict__ out, long long out_elems) {
    if (threadIdx.x == 0 && blockIdx.x == 0) {
        double lb = 0.0;
        for (int e = 0; e < E_EXP; e++) {
            double f = (double)g_cnt[e] / (double)(T_TOK * KSEL);
            double P = g_psum[e] / (double)T_TOK;
            lb += f * P;
        }
        lb *= (double)E_EXP;
        double z = g_zsum / (double)T_TOK;
        double aux = 0.01 * lb + 0.001 * z;
        long long idx = (long long)T_TOK * D_DIM;
        if (out_elems > idx) out[idx] = (float)aux;
    }
}

extern "C" void kernel_launch(void* const* d_in, const int* in_sizes, int n_in,
                              void* d_out, int out_size) {
    const float* x  = (const float*)d_in[0];
    const float* Wr = (const float*)d_in[1];
    const float* Wg = (const float*)d_in[2];
    const float* Wu = (const float*)d_in[3];
    const float* Wd = (const float*)d_in[4];
    float* out = (float*)d_out;

    cudaMemsetAsync(out, 0, (size_t)out_size * sizeof(float), 0);
    init_kernel<<<1, 32>>>();
    router_kernel<<<128, 256>>>(x, Wr);
    dim3 g1(F_DIM / BN, CAP / BM, E_EXP);
    gemm1_kernel<<<g1, 256>>>(x, Wg, Wu);
    dim3 g2(D_DIM / BN, CAP / BM, E_EXP);
    gemm2_kernel<<<g2, 256>>>(Wd, out);
    finalize_kernel<<<1, 32>>>(out, (long long)out_size);
}